// round 15
// baseline (speedup 1.0000x reference)
#include <cuda_runtime.h>
#include <cuda_bf16.h>
#include <cstdint>

// Only Z0[:,:,-1] = conv(X0, t=10) is nonzero.  Softmax degree-norm is a no-op.
// R15: split kernels (low regs) + saturating grids. Accumulators are zeroed by
// combine at end of each replay (static zero-init covers the first run).

// ---------------- device scratch ----------------
__device__ float g_obs2[2 * 8192];     // MLP input rows t=9,10
__device__ float g_s1[2 * 2048];       // accum; zeroed by combine
__device__ float g_s2[2 * 2048];       // accum; zeroed by combine
__device__ float g_s3[2 * 12288];      // accum; row0=X9, row1=X10 (pre-bias/relu)
__device__ float g_sph[12 * 256];      // accum; zeroed by combine
__device__ float g_tph[256];           // plain store (pre-bias)
__device__ float g_ua[12288 * 13];     // U pre-act accum [j][q0..11, tp]; zeroed by combine
__device__ float g_U[3 * 1024 * 12];   // [c][n][tau], c = feat-9
__device__ float g_Y[1024 * 12];
__device__ float g_G[3 * 1024 * 12];   // normalized (A@X) rows

// ---------------- prep: obs gather + out tail zero + sh (fused) ------------
__global__ void prep_kernel(const float* __restrict__ obs,
                            float* __restrict__ out,
                            const float* __restrict__ li,
                            const float* __restrict__ gs_w1,
                            const float* __restrict__ tf,
                            const float* __restrict__ gt_w1,
                            const float* __restrict__ gt_b1) {
    int idx = blockIdx.x * blockDim.x + threadIdx.x;
    if (idx < 16384) {
        int m = idx >> 13, k = idx & 8191;
        int n = k >> 3, d = k & 7;
        g_obs2[idx] = obs[n * 96 + d * 12 + 9 + m];
    } else if (idx < 16384 + 36864) {
        out[12288 + (idx - 16384)] = 0.0f;
    }
    // sh work on blocks 0..96 (atomics land on combine-zeroed g_sph)
    int t = threadIdx.x;
    if (blockIdx.x < 96) {
        int tau = blockIdx.x >> 3, kc = blockIdx.x & 7;
        const float* lr = li + tau * 1024 + kc * 128;
        const float* w  = gs_w1 + (size_t)(kc * 128) * 256 + t;
        float acc = 0.0f;
#pragma unroll 16
        for (int k = 0; k < 128; ++k) acc += lr[k] * w[(size_t)k * 256];
        atomicAdd(&g_sph[tau * 256 + t], acc);
    } else if (blockIdx.x == 96) {
        float acc = 0.0f;
#pragma unroll
        for (int k = 0; k < 36; ++k) acc += tf[k] * gt_w1[k * 256 + t];
        g_tph[t] = acc + gt_b1[t];   // pre-relu
    }
}

// ---------------- U pre-act: split-K x4, coalesced, atomic accum ------------
__global__ void u_kernel(const float* __restrict__ gs_w2,
                         const float* __restrict__ gs_b1,
                         const float* __restrict__ gt_w2) {
    __shared__ float sa[12 * 64];
    __shared__ float sat[64];
    int tid = threadIdx.x;
    int cb = blockIdx.x % 48;           // col block (256 cols)
    int kc = blockIdx.x / 48;           // 0..3 (64 k's each)
    if (tid < 64) sat[tid] = fmaxf(g_tph[kc * 64 + tid], 0.0f);
    for (int i = tid; i < 12 * 64; i += 256) {
        int q = i >> 6, kk = i & 63;
        sa[i] = fmaxf(g_sph[q * 256 + kc * 64 + kk] + gs_b1[kc * 64 + kk], 0.0f);
    }
    __syncthreads();

    int j = cb * 256 + tid;
    float acc[12];
#pragma unroll
    for (int q = 0; q < 12; ++q) acc[q] = 0.0f;
    float tp = 0.0f;
    const float* wg = gs_w2 + (size_t)(kc * 64) * 12288 + j;
    const float* wt = gt_w2 + (size_t)(kc * 64) * 12288 + j;
#pragma unroll 4
    for (int kk = 0; kk < 64; ++kk) {
        float w  = wg[(size_t)kk * 12288];
        float w2 = wt[(size_t)kk * 12288];
        tp += sat[kk] * w2;
#pragma unroll
        for (int q = 0; q < 12; ++q) acc[q] += sa[q * 64 + kk] * w;
    }
    float* ua = g_ua + (size_t)j * 13;
#pragma unroll
    for (int q = 0; q < 12; ++q) atomicAdd(ua + q, acc[q]);
    atomicAdd(ua + 12, tp);
}

// ---------------- U finalize + Y ----------------
__global__ void ufin_kernel(const float* __restrict__ gs_b2,
                            const float* __restrict__ gt_b2,
                            const float* __restrict__ Bm) {
    int idx = blockIdx.x * blockDim.x + threadIdx.x;   // 0..3071
    if (idx >= 3072) return;
    int n = idx / 3, c = idx % 3;
    int j = n * 12 + 9 + c;
    const float* ua = g_ua + (size_t)j * 13;
    float tpv = fmaxf(ua[12] + gt_b2[j], 0.0f);
    float bsp = gs_b2[j];
    float u[12];
#pragma unroll
    for (int q = 0; q < 12; ++q) {
        u[q] = fmaxf(ua[q] + bsp, 0.0f) + tpv;
        g_U[c * 12288 + n * 12 + q] = u[q];
    }
    if (c == 1) {
#pragma unroll
        for (int p = 0; p < 12; ++p) {
            float y = 0.0f;
#pragma unroll
            for (int q = 0; q < 12; ++q) y += Bm[p * 12 + q] * u[q];
            g_Y[n * 12 + p] = y;
        }
    }
}

// ---------------- split-K GEMV (M=2), bias+relu fused on A -----------------
template<int K, int N, bool RELU>
__device__ __forceinline__ void gemv_body(const float* __restrict__ A,
                                          const float* __restrict__ bias,
                                          const float* __restrict__ W,
                                          float* __restrict__ S, int kchunk) {
    int col = (blockIdx.x * blockDim.x + threadIdx.x) * 4;
    int k0  = blockIdx.y * kchunk;
    float a00 = 0, a01 = 0, a02 = 0, a03 = 0;
    float a10 = 0, a11 = 0, a12 = 0, a13 = 0;
#pragma unroll 8
    for (int k = k0; k < k0 + kchunk; ++k) {
        const float4 w = *reinterpret_cast<const float4*>(W + (size_t)k * N + col);
        float x0 = A[k], x1 = A[K + k];
        if (RELU) {
            float bb = bias[k];
            x0 = fmaxf(x0 + bb, 0.0f); x1 = fmaxf(x1 + bb, 0.0f);
        }
        a00 += x0 * w.x; a01 += x0 * w.y; a02 += x0 * w.z; a03 += x0 * w.w;
        a10 += x1 * w.x; a11 += x1 * w.y; a12 += x1 * w.z; a13 += x1 * w.w;
    }
    atomicAdd(S + col + 0, a00); atomicAdd(S + col + 1, a01);
    atomicAdd(S + col + 2, a02); atomicAdd(S + col + 3, a03);
    atomicAdd(S + N + col + 0, a10); atomicAdd(S + N + col + 1, a11);
    atomicAdd(S + N + col + 2, a12); atomicAdd(S + N + col + 3, a13);
}

__global__ void gemv1_kernel(const float* __restrict__ W) {
    gemv_body<8192, 2048, false>(g_obs2, nullptr, W, g_s1, 32);
}
__global__ void gemv2_kernel(const float* __restrict__ W,
                             const float* __restrict__ b1) {
    gemv_body<2048, 2048, true>(g_s1, b1, W, g_s2, 16);
}
__global__ void gemv3_kernel(const float* __restrict__ W,
                             const float* __restrict__ b2) {
    gemv_body<2048, 12288, true>(g_s2, b2, W, g_s3, 16);
}

// ---------------- adjacency: warp per (ap,row), smem-staged ----------------
#define ADJ_NTHR 512
#define ADJ_NWARP (148 * (ADJ_NTHR / 32))

__device__ __forceinline__ float4 relu4b(float4 v, float4 b) {
    v.x = fmaxf(v.x + b.x, 0.0f); v.y = fmaxf(v.y + b.y, 0.0f);
    v.z = fmaxf(v.z + b.z, 0.0f); v.w = fmaxf(v.w + b.w, 0.0f);
    return v;
}

__global__ void __launch_bounds__(ADJ_NTHR, 1)
adj_kernel(const float* __restrict__ b3) {
    extern __shared__ float sm[];
    float* sY   = sm;
    float* sX10 = sm + 12288;
    float* sX9  = sm + 24576;
    int tid = threadIdx.x;
    int gw = blockIdx.x * (ADJ_NTHR / 32) + (tid >> 5);
    int lane = tid & 31;

    for (int i = tid; i < 12288 / 4; i += ADJ_NTHR) {
        ((float4*)sY)[i] = ((const float4*)g_Y)[i];
        float4 bb = ((const float4*)b3)[i % 3072];
        ((float4*)sX10)[i] = relu4b(((const float4*)(g_s3 + 12288))[i], bb);
        ((float4*)sX9)[i]  = relu4b(((const float4*)g_s3)[i], bb);
    }
    __syncthreads();

    for (int task = gw; task < 3072; task += ADJ_NWARP) {
        int ap = task >> 10;
        int i = task & 1023;
        int cidx = (ap == 0) ? 1 : (ap == 1 ? 0 : 2);   // a = 10,9,11
        const float* sX = (ap == 0) ? sX10 : sX9;
        float u[12];
#pragma unroll
        for (int q = 0; q < 12; ++q) u[q] = g_U[cidx * 12288 + i * 12 + q];
        float g[12];
#pragma unroll
        for (int q = 0; q < 12; ++q) g[q] = 0.0f;
        float rs = 0.0f;
        for (int j = lane; j < 1024; j += 32) {
            const float4* yr = (const float4*)(sY + j * 12);
            float4 ya = yr[0], yb = yr[1], yc = yr[2];
            float s = u[0]*ya.x + u[1]*ya.y + u[2] *ya.z + u[3] *ya.w
                    + u[4]*yb.x + u[5]*yb.y + u[6] *yb.z + u[7] *yb.w
                    + u[8]*yc.x + u[9]*yc.y + u[10]*yc.z + u[11]*yc.w;
            s = (s >= 0.05f) ? s : 0.0f;
            float e = __expf(s);
            rs += e;
            const float4* xr = (const float4*)(sX + j * 12);
            float4 xa = xr[0], xb = xr[1], xc = xr[2];
            g[0] += e*xa.x; g[1] += e*xa.y; g[2] += e*xa.z; g[3] += e*xa.w;
            g[4] += e*xb.x; g[5] += e*xb.y; g[6] += e*xb.z; g[7] += e*xb.w;
            g[8] += e*xc.x; g[9] += e*xc.y; g[10]+= e*xc.z; g[11]+= e*xc.w;
        }
#pragma unroll
        for (int o = 16; o; o >>= 1) {
            rs += __shfl_xor_sync(0xffffffffu, rs, o);
#pragma unroll
            for (int q = 0; q < 12; ++q)
                g[q] += __shfl_xor_sync(0xffffffffu, g[q], o);
        }
        if (lane == 0) {
            float inv = 1.0f / rs;
            float* G = g_G + task * 12;
#pragma unroll
            for (int q = 0; q < 12; ++q) G[q] = g[q] * inv;
        }
    }
}

// ---------------- combine + re-zero all accumulators ----------------
__global__ void combine_kernel(const float* __restrict__ Wf,
                               const float* __restrict__ Wb,
                               const float* __restrict__ bvec,
                               float* __restrict__ out) {
    int idx = blockIdx.x * blockDim.x + threadIdx.x;
    if (idx < 12288) {
        int n = idx / 12, f = idx % 12;
        float acc1 = bvec[f], acc2 = bvec[f];
#pragma unroll
        for (int q = 0; q < 12; ++q) {
            acc1 += g_G[n * 12 + q] * (Wf[q * 12 + f] + Wb[q * 12 + f]);
            acc2 += g_G[(1024 + n) * 12 + q] * Wf[144 + q * 12 + f]
                  + g_G[(2048 + n) * 12 + q] * Wb[144 + q * 12 + f];
        }
        out[idx] = fmaxf(acc1, 0.0f) + fmaxf(acc2, 0.0f);
    } else {
        int i = idx - 12288;                  // zero 195584 accum floats
        if (i < 4096)            g_s1[i] = 0.0f;
        else if (i < 8192)       g_s2[i - 4096] = 0.0f;
        else if (i < 32768)      g_s3[i - 8192] = 0.0f;
        else if (i < 35840)      g_sph[i - 32768] = 0.0f;
        else if (i < 195584)     g_ua[i - 35840] = 0.0f;
    }
}

#define ADJ_SMEM (3 * 12288 * sizeof(float))

// ---------------- launch ----------------
extern "C" void kernel_launch(void* const* d_in, const int* in_sizes, int n_in,
                              void* d_out, int out_size) {
    const float* obs    = (const float*)d_in[0];
    const float* tf     = (const float*)d_in[1];
    const float* fc_w1  = (const float*)d_in[2];
    const float* fc_b1  = (const float*)d_in[3];
    const float* fc_w2  = (const float*)d_in[4];
    const float* fc_b2  = (const float*)d_in[5];
    const float* fc_w3  = (const float*)d_in[6];
    const float* fc_b3  = (const float*)d_in[7];
    const float* Wf     = (const float*)d_in[8];
    const float* Wb     = (const float*)d_in[9];
    const float* bvec   = (const float*)d_in[10];
    const float* li     = (const float*)d_in[11];
    const float* gs_w1  = (const float*)d_in[12];
    const float* gs_b1  = (const float*)d_in[13];
    const float* gs_w2  = (const float*)d_in[14];
    const float* gs_b2  = (const float*)d_in[15];
    const float* gt_w1  = (const float*)d_in[16];
    const float* gt_b1  = (const float*)d_in[17];
    const float* gt_w2  = (const float*)d_in[18];
    const float* gt_b2  = (const float*)d_in[19];
    const float* Bm     = (const float*)d_in[20];
    float* out = (float*)d_out;

    cudaFuncSetAttribute(adj_kernel,
                         cudaFuncAttributeMaxDynamicSharedMemorySize, ADJ_SMEM);

    prep_kernel<<<208, 256>>>(obs, out, li, gs_w1, tf, gt_w1, gt_b1);
    u_kernel<<<192, 256>>>(gs_w2, gs_b1, gt_w2);
    ufin_kernel<<<12, 256>>>(gs_b2, gt_b2, Bm);

    gemv1_kernel<<<dim3(2, 256), 256>>>(fc_w1);
    gemv2_kernel<<<dim3(2, 128), 256>>>(fc_w2, fc_b1);
    gemv3_kernel<<<dim3(12, 128), 256>>>(fc_w3, fc_b2);

    adj_kernel<<<148, ADJ_NTHR, ADJ_SMEM>>>(fc_b3);
    combine_kernel<<<406, 512>>>(Wf, Wb, bvec, out);
}

// round 17
// speedup vs baseline: 1.1369x; 1.1369x over previous
#include <cuda_runtime.h>
#include <cuda_bf16.h>
#include <cstdint>

// Only Z0[:,:,-1] = conv(X0, t=10) is nonzero.  Softmax degree-norm is a no-op.
// R17 = R16 + fix: u_kernel smem staging loop strided (384 > 256 threads).
// Explicit 4-deep software-pipelined GEMVs; accumulators zeroed by combine.

// ---------------- device scratch ----------------
__device__ float g_obs2[2 * 8192];     // MLP input rows t=9,10
__device__ float g_s1[2 * 2048];       // accum; zeroed by combine
__device__ float g_s2[2 * 2048];       // accum; zeroed by combine
__device__ float g_s3[2 * 12288];      // accum; row0=X9, row1=X10 (pre-bias/relu)
__device__ float g_sph[12 * 256];      // accum; zeroed by combine
__device__ float g_tph[256];           // plain store (pre-bias)
__device__ float g_ua[3072 * 13];      // U pre-act accum; zeroed by combine
__device__ float g_U[3 * 1024 * 12];   // [c][n][tau], c = feat-9
__device__ float g_Y[1024 * 12];
__device__ float g_G[3 * 1024 * 12];   // normalized (A@X) rows

// ---------------- prep: obs gather + out tail zero + sh (fused) ------------
__global__ void prep_kernel(const float* __restrict__ obs,
                            float* __restrict__ out,
                            const float* __restrict__ li,
                            const float* __restrict__ gs_w1,
                            const float* __restrict__ tf,
                            const float* __restrict__ gt_w1,
                            const float* __restrict__ gt_b1) {
    int idx = blockIdx.x * blockDim.x + threadIdx.x;
    if (idx < 16384) {
        int m = idx >> 13, k = idx & 8191;
        int n = k >> 3, d = k & 7;
        g_obs2[idx] = obs[n * 96 + d * 12 + 9 + m];
    } else if (idx < 16384 + 36864) {
        out[12288 + (idx - 16384)] = 0.0f;
    }
    int t = threadIdx.x;
    if (blockIdx.x < 96) {          // sph split-K: atomics on combine-zeroed buf
        int tau = blockIdx.x >> 3, kc = blockIdx.x & 7;
        const float* lr = li + tau * 1024 + kc * 128;
        const float* w  = gs_w1 + (size_t)(kc * 128) * 256 + t;
        float acc = 0.0f;
#pragma unroll 16
        for (int k = 0; k < 128; ++k) acc += lr[k] * w[(size_t)k * 256];
        atomicAdd(&g_sph[tau * 256 + t], acc);
    } else if (blockIdx.x == 96) {
        float acc = 0.0f;
#pragma unroll
        for (int k = 0; k < 36; ++k) acc += tf[k] * gt_w1[k * 256 + t];
        g_tph[t] = acc + gt_b1[t];   // pre-relu
    }
}

// ---------------- U pre-act: only needed cols, split-K x8 ------------------
__global__ void u_kernel(const float* __restrict__ gs_w2,
                         const float* __restrict__ gs_b1,
                         const float* __restrict__ gt_w2) {
    __shared__ float sa[12 * 32];
    __shared__ float sat[32];
    int tid = threadIdx.x;
    int cb = blockIdx.x % 12;            // 256 j' each
    int kc = blockIdx.x / 12;            // 0..7 (32 k's each)
    if (tid < 32) sat[tid] = fmaxf(g_tph[kc * 32 + tid], 0.0f);
    for (int i = tid; i < 384; i += 256) {   // FIX (R16): 384 > 256 -> stride!
        int q = i >> 5, kk = i & 31;
        sa[i] = fmaxf(g_sph[q * 256 + kc * 32 + kk] + gs_b1[kc * 32 + kk], 0.0f);
    }
    __syncthreads();

    int jp = cb * 256 + tid;             // 0..3071
    int n = jp / 3, c = jp % 3;
    int j = n * 12 + 9 + c;
    float acc[12];
#pragma unroll
    for (int q = 0; q < 12; ++q) acc[q] = 0.0f;
    float tp = 0.0f;
    const float* wg = gs_w2 + (size_t)(kc * 32) * 12288 + j;
    const float* wt = gt_w2 + (size_t)(kc * 32) * 12288 + j;
#pragma unroll 4
    for (int kk = 0; kk < 32; ++kk) {
        float w  = wg[(size_t)kk * 12288];
        float w2 = wt[(size_t)kk * 12288];
        tp += sat[kk] * w2;
#pragma unroll
        for (int q = 0; q < 12; ++q) acc[q] += sa[q * 32 + kk] * w;
    }
    float* ua = g_ua + (size_t)jp * 13;
#pragma unroll
    for (int q = 0; q < 12; ++q) atomicAdd(ua + q, acc[q]);
    atomicAdd(ua + 12, tp);
}

// ---------------- U finalize + Y ----------------
__global__ void ufin_kernel(const float* __restrict__ gs_b2,
                            const float* __restrict__ gt_b2,
                            const float* __restrict__ Bm) {
    int idx = blockIdx.x * blockDim.x + threadIdx.x;   // jp = 0..3071
    if (idx >= 3072) return;
    int n = idx / 3, c = idx % 3;
    int j = n * 12 + 9 + c;
    const float* ua = g_ua + (size_t)idx * 13;
    float tpv = fmaxf(ua[12] + gt_b2[j], 0.0f);
    float bsp = gs_b2[j];
    float u[12];
#pragma unroll
    for (int q = 0; q < 12; ++q) {
        u[q] = fmaxf(ua[q] + bsp, 0.0f) + tpv;
        g_U[c * 12288 + n * 12 + q] = u[q];
    }
    if (c == 1) {
#pragma unroll
        for (int p = 0; p < 12; ++p) {
            float y = 0.0f;
#pragma unroll
            for (int q = 0; q < 12; ++q) y += Bm[p * 12 + q] * u[q];
            g_Y[n * 12 + p] = y;
        }
    }
}

// -------- 4-deep software-pipelined split-K GEMV (M=2, 4 cols/thread) ------
template<int K, int N, int CH, bool RELU>
__device__ __forceinline__ void gemv_pipe(const float* __restrict__ A,
                                          const float* __restrict__ bias,
                                          const float* __restrict__ W,
                                          float* __restrict__ S) {
    const int col = (blockIdx.x * blockDim.x + threadIdx.x) * 4;
    const int k0  = blockIdx.y * CH;
    const float* Wp = W + (size_t)k0 * N + col;
    constexpr int NIT = CH / 4;

    float4 w0 = *(const float4*)(Wp);
    float4 w1 = *(const float4*)(Wp + (size_t)N);
    float4 w2 = *(const float4*)(Wp + 2 * (size_t)N);
    float4 w3 = *(const float4*)(Wp + 3 * (size_t)N);

    float a00 = 0, a01 = 0, a02 = 0, a03 = 0;
    float a10 = 0, a11 = 0, a12 = 0, a13 = 0;

#pragma unroll
    for (int it = 0; it < NIT; ++it) {
        float4 n0, n1, n2, n3;
        if (it + 1 < NIT) {
            const float* Wn = Wp + (size_t)(it + 1) * 4 * N;
            n0 = *(const float4*)(Wn);
            n1 = *(const float4*)(Wn + (size_t)N);
            n2 = *(const float4*)(Wn + 2 * (size_t)N);
            n3 = *(const float4*)(Wn + 3 * (size_t)N);
        }
        const int kb = k0 + it * 4;
        float x00 = A[kb],     x01 = A[kb + 1],     x02 = A[kb + 2],     x03 = A[kb + 3];
        float x10 = A[K + kb], x11 = A[K + kb + 1], x12 = A[K + kb + 2], x13 = A[K + kb + 3];
        if (RELU) {
            float b0 = bias[kb], bb1 = bias[kb + 1], bb2 = bias[kb + 2], bb3 = bias[kb + 3];
            x00 = fmaxf(x00 + b0, 0.0f); x01 = fmaxf(x01 + bb1, 0.0f);
            x02 = fmaxf(x02 + bb2, 0.0f); x03 = fmaxf(x03 + bb3, 0.0f);
            x10 = fmaxf(x10 + b0, 0.0f); x11 = fmaxf(x11 + bb1, 0.0f);
            x12 = fmaxf(x12 + bb2, 0.0f); x13 = fmaxf(x13 + bb3, 0.0f);
        }
        a00 += x00 * w0.x; a01 += x00 * w0.y; a02 += x00 * w0.z; a03 += x00 * w0.w;
        a10 += x10 * w0.x; a11 += x10 * w0.y; a12 += x10 * w0.z; a13 += x10 * w0.w;
        a00 += x01 * w1.x; a01 += x01 * w1.y; a02 += x01 * w1.z; a03 += x01 * w1.w;
        a10 += x11 * w1.x; a11 += x11 * w1.y; a12 += x11 * w1.z; a13 += x11 * w1.w;
        a00 += x02 * w2.x; a01 += x02 * w2.y; a02 += x02 * w2.z; a03 += x02 * w2.w;
        a10 += x12 * w2.x; a11 += x12 * w2.y; a12 += x12 * w2.z; a13 += x12 * w2.w;
        a00 += x03 * w3.x; a01 += x03 * w3.y; a02 += x03 * w3.z; a03 += x03 * w3.w;
        a10 += x13 * w3.x; a11 += x13 * w3.y; a12 += x13 * w3.z; a13 += x13 * w3.w;
        w0 = n0; w1 = n1; w2 = n2; w3 = n3;
    }
    atomicAdd(S + col + 0, a00); atomicAdd(S + col + 1, a01);
    atomicAdd(S + col + 2, a02); atomicAdd(S + col + 3, a03);
    atomicAdd(S + N + col + 0, a10); atomicAdd(S + N + col + 1, a11);
    atomicAdd(S + N + col + 2, a12); atomicAdd(S + N + col + 3, a13);
}

__global__ void gemv1_kernel(const float* __restrict__ W) {
    gemv_pipe<8192, 2048, 32, false>(g_obs2, nullptr, W, g_s1);
}
__global__ void gemv2_kernel(const float* __restrict__ W,
                             const float* __restrict__ b1) {
    gemv_pipe<2048, 2048, 16, true>(g_s1, b1, W, g_s2);
}
__global__ void gemv3_kernel(const float* __restrict__ W,
                             const float* __restrict__ b2) {
    gemv_pipe<2048, 12288, 16, true>(g_s2, b2, W, g_s3);
}

// ---------------- adjacency: warp per (ap,row), smem-staged ----------------
#define ADJ_NTHR 512
#define ADJ_NWARP (148 * (ADJ_NTHR / 32))

__device__ __forceinline__ float4 relu4b(float4 v, float4 b) {
    v.x = fmaxf(v.x + b.x, 0.0f); v.y = fmaxf(v.y + b.y, 0.0f);
    v.z = fmaxf(v.z + b.z, 0.0f); v.w = fmaxf(v.w + b.w, 0.0f);
    return v;
}

__global__ void __launch_bounds__(ADJ_NTHR, 1)
adj_kernel(const float* __restrict__ b3) {
    extern __shared__ float sm[];
    float* sY   = sm;
    float* sX10 = sm + 12288;
    float* sX9  = sm + 24576;
    int tid = threadIdx.x;
    int gw = blockIdx.x * (ADJ_NTHR / 32) + (tid >> 5);
    int lane = tid & 31;

    for (int i = tid; i < 12288 / 4; i += ADJ_NTHR) {
        ((float4*)sY)[i] = ((const float4*)g_Y)[i];
        float4 bb = ((const float4*)b3)[i % 3072];
        ((float4*)sX10)[i] = relu4b(((const float4*)(g_s3 + 12288))[i], bb);
        ((float4*)sX9)[i]  = relu4b(((const float4*)g_s3)[i], bb);
    }
    __syncthreads();

    for (int task = gw; task < 3072; task += ADJ_NWARP) {
        int ap = task >> 10;
        int i = task & 1023;
        int cidx = (ap == 0) ? 1 : (ap == 1 ? 0 : 2);   // a = 10,9,11
        const float* sX = (ap == 0) ? sX10 : sX9;
        float u[12];
#pragma unroll
        for (int q = 0; q < 12; ++q) u[q] = g_U[cidx * 12288 + i * 12 + q];
        float g[12];
#pragma unroll
        for (int q = 0; q < 12; ++q) g[q] = 0.0f;
        float rs = 0.0f;
        for (int j = lane; j < 1024; j += 32) {
            const float4* yr = (const float4*)(sY + j * 12);
            float4 ya = yr[0], yb = yr[1], yc = yr[2];
            float s = u[0]*ya.x + u[1]*ya.y + u[2] *ya.z + u[3] *ya.w
                    + u[4]*yb.x + u[5]*yb.y + u[6] *yb.z + u[7] *yb.w
                    + u[8]*yc.x + u[9]*yc.y + u[10]*yc.z + u[11]*yc.w;
            s = (s >= 0.05f) ? s : 0.0f;
            float e = __expf(s);
            rs += e;
            const float4* xr = (const float4*)(sX + j * 12);
            float4 xa = xr[0], xb = xr[1], xc = xr[2];
            g[0] += e*xa.x; g[1] += e*xa.y; g[2] += e*xa.z; g[3] += e*xa.w;
            g[4] += e*xb.x; g[5] += e*xb.y; g[6] += e*xb.z; g[7] += e*xb.w;
            g[8] += e*xc.x; g[9] += e*xc.y; g[10]+= e*xc.z; g[11]+= e*xc.w;
        }
#pragma unroll
        for (int o = 16; o; o >>= 1) {
            rs += __shfl_xor_sync(0xffffffffu, rs, o);
#pragma unroll
            for (int q = 0; q < 12; ++q)
                g[q] += __shfl_xor_sync(0xffffffffu, g[q], o);
        }
        if (lane == 0) {
            float inv = 1.0f / rs;
            float* G = g_G + task * 12;
#pragma unroll
            for (int q = 0; q < 12; ++q) G[q] = g[q] * inv;
        }
    }
}

// ---------------- combine + re-zero all accumulators ----------------
__global__ void combine_kernel(const float* __restrict__ Wf,
                               const float* __restrict__ Wb,
                               const float* __restrict__ bvec,
                               float* __restrict__ out) {
    int idx = blockIdx.x * blockDim.x + threadIdx.x;
    if (idx < 12288) {
        int n = idx / 12, f = idx % 12;
        float acc1 = bvec[f], acc2 = bvec[f];
#pragma unroll
        for (int q = 0; q < 12; ++q) {
            acc1 += g_G[n * 12 + q] * (Wf[q * 12 + f] + Wb[q * 12 + f]);
            acc2 += g_G[(1024 + n) * 12 + q] * Wf[144 + q * 12 + f]
                  + g_G[(2048 + n) * 12 + q] * Wb[144 + q * 12 + f];
        }
        out[idx] = fmaxf(acc1, 0.0f) + fmaxf(acc2, 0.0f);
    } else {
        int i = idx - 12288;                  // zero 75776 accum floats
        if (i < 4096)        g_s1[i] = 0.0f;
        else if (i < 8192)   g_s2[i - 4096] = 0.0f;
        else if (i < 32768)  g_s3[i - 8192] = 0.0f;
        else if (i < 35840)  g_sph[i - 32768] = 0.0f;
        else if (i < 75776)  g_ua[i - 35840] = 0.0f;
    }
}

#define ADJ_SMEM (3 * 12288 * sizeof(float))

// ---------------- launch ----------------
extern "C" void kernel_launch(void* const* d_in, const int* in_sizes, int n_in,
                              void* d_out, int out_size) {
    const float* obs    = (const float*)d_in[0];
    const float* tf     = (const float*)d_in[1];
    const float* fc_w1  = (const float*)d_in[2];
    const float* fc_b1  = (const float*)d_in[3];
    const float* fc_w2  = (const float*)d_in[4];
    const float* fc_b2  = (const float*)d_in[5];
    const float* fc_w3  = (const float*)d_in[6];
    const float* fc_b3  = (const float*)d_in[7];
    const float* Wf     = (const float*)d_in[8];
    const float* Wb     = (const float*)d_in[9];
    const float* bvec   = (const float*)d_in[10];
    const float* li     = (const float*)d_in[11];
    const float* gs_w1  = (const float*)d_in[12];
    const float* gs_b1  = (const float*)d_in[13];
    const float* gs_w2  = (const float*)d_in[14];
    const float* gs_b2  = (const float*)d_in[15];
    const float* gt_w1  = (const float*)d_in[16];
    const float* gt_b1  = (const float*)d_in[17];
    const float* gt_w2  = (const float*)d_in[18];
    const float* gt_b2  = (const float*)d_in[19];
    const float* Bm     = (const float*)d_in[20];
    float* out = (float*)d_out;

    cudaFuncSetAttribute(adj_kernel,
                         cudaFuncAttributeMaxDynamicSharedMemorySize, ADJ_SMEM);

    prep_kernel<<<208, 256>>>(obs, out, li, gs_w1, tf, gt_w1, gt_b1);
    u_kernel<<<96, 256>>>(gs_w2, gs_b1, gt_w2);
    ufin_kernel<<<12, 256>>>(gs_b2, gt_b2, Bm);

    gemv1_kernel<<<dim3(2, 256), 256>>>(fc_w1);
    gemv2_kernel<<<dim3(2, 128), 256>>>(fc_w2, fc_b1);
    gemv3_kernel<<<dim3(12, 128), 256>>>(fc_w3, fc_b2);

    adj_kernel<<<148, ADJ_NTHR, ADJ_SMEM>>>(fc_b3);
    combine_kernel<<<172, 512>>>(Wf, Wb, bvec, out);
}